// round 3
// baseline (speedup 1.0000x reference)
#include <cuda_runtime.h>
#include <math.h>
#include <stdint.h>

// Problem constants
#define BATCH 2
#define SEQ   2048
#define DMODEL 1024
#define NHEAD 16
#define DHEAD 64
#define NTOK  (BATCH*SEQ)          // 4096
#define QKVN  (3*DMODEL)           // 3072

// Scratch (allocation-free rule: __device__ globals)
__device__ float g_qkv[(size_t)NTOK * QKVN];   // [4096][3072]
__device__ float g_ao [(size_t)NTOK * DMODEL]; // [4096][1024] attention output (b,s,h*64+d)

// ---------------------------------------------------------------------------
// Generic SGEMM: C[M,N] = A[M,K] @ W[N,K]^T + bias[N]
// 128x128 tile, BK=16, 256 threads, 8x8 per thread.
// ---------------------------------------------------------------------------
#define TM 128
#define TN 128
#define TK 16

__global__ __launch_bounds__(256, 2)
void sgemm_bias(const float* __restrict__ A, const float* __restrict__ W,
                const float* __restrict__ bias, float* __restrict__ C,
                int M, int N, int K)
{
    __shared__ float As[TK][TM];
    __shared__ float Bs[TK][TN];

    const int tid = threadIdx.x;
    const int tx  = tid & 15;      // 0..15 -> N
    const int ty  = tid >> 4;      // 0..15 -> M
    const int bm  = blockIdx.y * TM;
    const int bn  = blockIdx.x * TN;

    float acc[8][8];
    #pragma unroll
    for (int i = 0; i < 8; i++)
        #pragma unroll
        for (int j = 0; j < 8; j++) acc[i][j] = 0.f;

    for (int k0 = 0; k0 < K; k0 += TK) {
        // Load A tile (128x16) and W tile (128x16), both transposed into smem.
        #pragma unroll
        for (int it = 0; it < 2; it++) {
            int idx = tid + it * 256;          // float4 index, 0..511
            int row = idx >> 2;                // 0..127
            int kq  = (idx & 3) << 2;          // 0,4,8,12
            float4 va = *(const float4*)&A[(size_t)(bm + row) * K + k0 + kq];
            As[kq + 0][row] = va.x; As[kq + 1][row] = va.y;
            As[kq + 2][row] = va.z; As[kq + 3][row] = va.w;
            float4 vb = *(const float4*)&W[(size_t)(bn + row) * K + k0 + kq];
            Bs[kq + 0][row] = vb.x; Bs[kq + 1][row] = vb.y;
            Bs[kq + 2][row] = vb.z; Bs[kq + 3][row] = vb.w;
        }
        __syncthreads();

        #pragma unroll
        for (int kk = 0; kk < TK; kk++) {
            float a[8], b[8];
            *(float4*)(a)     = *(float4*)&As[kk][ty * 8];
            *(float4*)(a + 4) = *(float4*)&As[kk][ty * 8 + 4];
            *(float4*)(b)     = *(float4*)&Bs[kk][tx * 8];
            *(float4*)(b + 4) = *(float4*)&Bs[kk][tx * 8 + 4];
            #pragma unroll
            for (int i = 0; i < 8; i++)
                #pragma unroll
                for (int j = 0; j < 8; j++)
                    acc[i][j] = fmaf(a[i], b[j], acc[i][j]);
        }
        __syncthreads();
    }

    #pragma unroll
    for (int i = 0; i < 8; i++) {
        int row = bm + ty * 8 + i;
        #pragma unroll
        for (int j = 0; j < 8; j++) {
            int col = bn + tx * 8 + j;
            C[(size_t)row * N + col] = acc[i][j] + bias[col];
        }
    }
}

// ---------------------------------------------------------------------------
// Flash attention: one block per (b*H + h, 64-query tile).
// 256 threads = 16x16, each owns a 4x4 fragment of the 64x64 tiles.
// qkv layout per token: [H][3*DHEAD] (q at +0, k at +64, v at +128 within head).
// Mask is read as 32-bit words, nonzero == true (works for int32 AND float32).
// ---------------------------------------------------------------------------
#define AQ 64
#define AK 64
#define QT_LD 68   // padded row length for Qt/Kt (d-major)
#define PS_LD 65   // padded row length for P

// smem floats: Qt 64*68, Kt 64*68, Vs 64*64, Ps 64*65, m/l/a 3*64
#define ATTN_SMEM_FLOATS (64*QT_LD*2 + 64*64 + 64*PS_LD + 3*64)
#define ATTN_SMEM_BYTES  (ATTN_SMEM_FLOATS * 4)

__global__ __launch_bounds__(256, 1)
void attn_kernel(const float* __restrict__ qkv,
                 const unsigned int* __restrict__ mask,
                 float* __restrict__ ao)
{
    extern __shared__ float sm[];
    float* Qt   = sm;                   // [64][68]  Qt[d][q]
    float* Kt   = Qt + 64 * QT_LD;      // [64][68]  Kt[d][k]
    float* Vs   = Kt + 64 * QT_LD;      // [64][64]  Vs[k][d]
    float* Ps   = Vs + 64 * 64;         // [64][65]  scores/probs [q][k]
    float* mrow = Ps + 64 * PS_LD;      // [64]
    float* lrow = mrow + 64;            // [64]
    float* arow = lrow + 64;            // [64]

    const int bh = blockIdx.y;
    const int b  = bh >> 4;
    const int h  = bh & 15;
    const int q0 = blockIdx.x * AQ;
    const int tid = threadIdx.x;
    const int tx = tid & 15;
    const int ty = tid >> 4;

    const float scale = 0.03125f;                       // 1024^-0.5
    const float slope = exp2f(-0.5f * (float)(h + 1));  // ALiBi slope

    const float* base = qkv + (size_t)b * SEQ * QKVN + h * (3 * DHEAD);

    // Load Q tile (d-major transposed)
    #pragma unroll
    for (int it = 0; it < 4; it++) {
        int idx = tid + it * 256;      // float4 units, 0..1023
        int q   = idx >> 4;            // 0..63
        int d4  = (idx & 15) << 2;     // 0..60
        float4 v = *(const float4*)&base[(size_t)(q0 + q) * QKVN + d4];
        Qt[(d4 + 0) * QT_LD + q] = v.x;
        Qt[(d4 + 1) * QT_LD + q] = v.y;
        Qt[(d4 + 2) * QT_LD + q] = v.z;
        Qt[(d4 + 3) * QT_LD + q] = v.w;
    }
    if (tid < 64) { mrow[tid] = -INFINITY; lrow[tid] = 0.f; }

    float O[4][4];
    #pragma unroll
    for (int i = 0; i < 4; i++)
        #pragma unroll
        for (int j = 0; j < 4; j++) O[i][j] = 0.f;

    __syncthreads();

    for (int k0 = 0; k0 < SEQ; k0 += AK) {
        // Load K (transposed) and V tiles
        #pragma unroll
        for (int it = 0; it < 4; it++) {
            int idx = tid + it * 256;
            int kr  = idx >> 4;
            int d4  = (idx & 15) << 2;
            const float* krow = &base[(size_t)(k0 + kr) * QKVN + DHEAD];
            float4 kv = *(const float4*)&krow[d4];
            Kt[(d4 + 0) * QT_LD + kr] = kv.x;
            Kt[(d4 + 1) * QT_LD + kr] = kv.y;
            Kt[(d4 + 2) * QT_LD + kr] = kv.z;
            Kt[(d4 + 3) * QT_LD + kr] = kv.w;
            float4 vv = *(const float4*)&krow[DHEAD + d4];
            *(float4*)&Vs[kr * 64 + d4] = vv;
        }
        __syncthreads();

        // S = Q @ K^T  (4x4 fragment per thread)
        float sc[4][4];
        #pragma unroll
        for (int i = 0; i < 4; i++)
            #pragma unroll
            for (int j = 0; j < 4; j++) sc[i][j] = 0.f;

        #pragma unroll
        for (int kk = 0; kk < 64; kk++) {
            float4 qa = *(float4*)&Qt[kk * QT_LD + ty * 4];
            float4 kb = *(float4*)&Kt[kk * QT_LD + tx * 4];
            float a[4] = {qa.x, qa.y, qa.z, qa.w};
            float bb[4] = {kb.x, kb.y, kb.z, kb.w};
            #pragma unroll
            for (int i = 0; i < 4; i++)
                #pragma unroll
                for (int j = 0; j < 4; j++)
                    sc[i][j] = fmaf(a[i], bb[j], sc[i][j]);
        }

        // scale + ALiBi + mask -> Ps   (mask: 32-bit word, nonzero == keep)
        #pragma unroll
        for (int i = 0; i < 4; i++) {
            int qg = q0 + ty * 4 + i;
            #pragma unroll
            for (int j = 0; j < 4; j++) {
                int kg = k0 + tx * 4 + j;
                float s = sc[i][j] * scale - slope * fabsf((float)(qg - kg));
                if (mask[b * SEQ + kg] == 0u) s = -3.0e38f;
                Ps[(ty * 4 + i) * PS_LD + tx * 4 + j] = s;
            }
        }
        __syncthreads();

        // Online softmax row pass (64 threads, one per query row)
        if (tid < 64) {
            int r = tid;
            float mo = mrow[r];
            float tm = -INFINITY;
            #pragma unroll 8
            for (int j = 0; j < 64; j++) tm = fmaxf(tm, Ps[r * PS_LD + j]);
            float mn = fmaxf(mo, tm);
            float a  = __expf(mo - mn);
            float sum = 0.f;
            #pragma unroll 8
            for (int j = 0; j < 64; j++) {
                float p = __expf(Ps[r * PS_LD + j] - mn);
                Ps[r * PS_LD + j] = p;
                sum += p;
            }
            lrow[r] = lrow[r] * a + sum;
            mrow[r] = mn;
            arow[r] = a;
        }
        __syncthreads();

        // O = O*alpha + P @ V
        float ai[4];
        #pragma unroll
        for (int i = 0; i < 4; i++) ai[i] = arow[ty * 4 + i];
        #pragma unroll
        for (int i = 0; i < 4; i++)
            #pragma unroll
            for (int j = 0; j < 4; j++) O[i][j] *= ai[i];

        #pragma unroll
        for (int kk = 0; kk < 64; kk++) {
            float p[4];
            #pragma unroll
            for (int i = 0; i < 4; i++) p[i] = Ps[(ty * 4 + i) * PS_LD + kk];
            float4 vv = *(float4*)&Vs[kk * 64 + tx * 4];
            float vj[4] = {vv.x, vv.y, vv.z, vv.w};
            #pragma unroll
            for (int i = 0; i < 4; i++)
                #pragma unroll
                for (int j = 0; j < 4; j++)
                    O[i][j] = fmaf(p[i], vj[j], O[i][j]);
        }
        __syncthreads();
    }

    // Finalize: divide by l, write to ao[b][s][h*64+d]
    float linv[4];
    #pragma unroll
    for (int i = 0; i < 4; i++) linv[i] = 1.f / lrow[ty * 4 + i];
    #pragma unroll
    for (int i = 0; i < 4; i++) {
        int sg = q0 + ty * 4 + i;
        #pragma unroll
        for (int j = 0; j < 4; j++) {
            int d = tx * 4 + j;
            ao[((size_t)(b * SEQ + sg)) * DMODEL + h * DHEAD + d] = O[i][j] * linv[i];
        }
    }
}

// ---------------------------------------------------------------------------
extern "C" void kernel_launch(void* const* d_in, const int* in_sizes, int n_in,
                              void* d_out, int out_size)
{
    const float* X     = (const float*)d_in[0];
    const unsigned int* mask = (const unsigned int*)d_in[1];
    const float* Wqkv  = (const float*)d_in[2];
    const float* bqkv  = (const float*)d_in[3];
    const float* Wproj = (const float*)d_in[4];
    const float* bproj = (const float*)d_in[5];
    float* out = (float*)d_out;

    float *qkv, *ao;
    cudaGetSymbolAddress((void**)&qkv, g_qkv);
    cudaGetSymbolAddress((void**)&ao,  g_ao);

    cudaFuncSetAttribute(attn_kernel, cudaFuncAttributeMaxDynamicSharedMemorySize,
                         ATTN_SMEM_BYTES);

    // 1) QKV projection: [4096,1024] @ [3072,1024]^T -> [4096,3072]
    sgemm_bias<<<dim3(QKVN / TN, NTOK / TM), 256>>>(X, Wqkv, bqkv, qkv,
                                                    NTOK, QKVN, DMODEL);
    // 2) Flash attention
    attn_kernel<<<dim3(SEQ / AQ, BATCH * NHEAD), 256, ATTN_SMEM_BYTES>>>(qkv, mask, ao);
    // 3) Output projection: [4096,1024] @ [1024,1024]^T -> [4096,1024]
    sgemm_bias<<<dim3(DMODEL / TN, NTOK / TM), 256>>>(ao, Wproj, bproj, out,
                                                      NTOK, DMODEL, DMODEL);
}

// round 4
// speedup vs baseline: 1.5582x; 1.5582x over previous
#include <cuda_runtime.h>
#include <math.h>
#include <stdint.h>

// Problem constants
#define BATCH 2
#define SEQ   2048
#define DMODEL 1024
#define NHEAD 16
#define DHEAD 64
#define NTOK  (BATCH*SEQ)          // 4096
#define QKVN  (3*DMODEL)           // 3072

// Scratch (allocation-free rule: __device__ globals)
__device__ float g_qkv[(size_t)NTOK * QKVN];   // [4096][3072]
__device__ float g_ao [(size_t)NTOK * DMODEL]; // [4096][1024]

__device__ __forceinline__ uint32_t f2tf32(float f) {
    uint32_t u;
    asm("cvt.rna.tf32.f32 %0, %1;" : "=r"(u) : "f"(f));
    return u;
}

__device__ __forceinline__ void mma_tf32(float c[4], const uint32_t a[4], const uint32_t b[2]) {
    asm volatile(
        "mma.sync.aligned.m16n8k8.row.col.f32.tf32.tf32.f32 "
        "{%0,%1,%2,%3}, {%4,%5,%6,%7}, {%8,%9}, {%0,%1,%2,%3};"
        : "+f"(c[0]), "+f"(c[1]), "+f"(c[2]), "+f"(c[3])
        : "r"(a[0]), "r"(a[1]), "r"(a[2]), "r"(a[3]), "r"(b[0]), "r"(b[1]));
}

// ---------------------------------------------------------------------------
// TF32 tensor-core GEMM: C[M,N] = A[M,K] @ W[N,K]^T + bias[N]
// 128x128 block tile, BK=32, 256 threads = 8 warps (4x2), warp tile 32x64.
// ---------------------------------------------------------------------------
#define GLD 36   // smem row length (32 + 4 pad) -> conflict-free frag loads

__global__ __launch_bounds__(256, 2)
void sgemm_tf32(const float* __restrict__ A, const float* __restrict__ W,
                const float* __restrict__ bias, float* __restrict__ C,
                int M, int N, int K)
{
    __shared__ uint32_t As[128][GLD];
    __shared__ uint32_t Ws[128][GLD];

    const int tid = threadIdx.x;
    const int l   = tid & 31;
    const int w   = tid >> 5;
    const int wm  = (w & 3) * 32;     // warp M offset in tile
    const int wn  = (w >> 2) * 64;    // warp N offset in tile
    const int bm  = blockIdx.y * 128;
    const int bn  = blockIdx.x * 128;
    const int g   = l >> 2;           // groupID 0..7
    const int tg  = l & 3;            // threadInGroup 0..3

    float acc[2][8][4];
    #pragma unroll
    for (int i = 0; i < 2; i++)
        #pragma unroll
        for (int j = 0; j < 8; j++)
            #pragma unroll
            for (int t = 0; t < 4; t++) acc[i][j][t] = 0.f;

    for (int k0 = 0; k0 < K; k0 += 32) {
        // Load 128x32 tiles of A and W, convert to tf32, store to smem.
        #pragma unroll
        for (int it = 0; it < 4; it++) {
            int idx = tid + it * 256;          // 0..1023 float4 slots
            int row = idx >> 3;                // 0..127
            int kq  = (idx & 7) << 2;          // 0,4,...,28
            float4 va = *(const float4*)&A[(size_t)(bm + row) * K + k0 + kq];
            uint4 ua = make_uint4(f2tf32(va.x), f2tf32(va.y), f2tf32(va.z), f2tf32(va.w));
            *(uint4*)&As[row][kq] = ua;
            float4 vb = *(const float4*)&W[(size_t)(bn + row) * K + k0 + kq];
            uint4 ub = make_uint4(f2tf32(vb.x), f2tf32(vb.y), f2tf32(vb.z), f2tf32(vb.w));
            *(uint4*)&Ws[row][kq] = ub;
        }
        __syncthreads();

        #pragma unroll
        for (int ks = 0; ks < 4; ks++) {
            int k8 = ks * 8;
            uint32_t af[2][4];
            #pragma unroll
            for (int mt = 0; mt < 2; mt++) {
                int r0 = wm + mt * 16 + g;
                af[mt][0] = As[r0    ][k8 + tg];
                af[mt][1] = As[r0 + 8][k8 + tg];
                af[mt][2] = As[r0    ][k8 + 4 + tg];
                af[mt][3] = As[r0 + 8][k8 + 4 + tg];
            }
            uint32_t bf[8][2];
            #pragma unroll
            for (int nt = 0; nt < 8; nt++) {
                int c0 = wn + nt * 8 + g;
                bf[nt][0] = Ws[c0][k8 + tg];
                bf[nt][1] = Ws[c0][k8 + 4 + tg];
            }
            #pragma unroll
            for (int mt = 0; mt < 2; mt++)
                #pragma unroll
                for (int nt = 0; nt < 8; nt++)
                    mma_tf32(acc[mt][nt], af[mt], bf[nt]);
        }
        __syncthreads();
    }

    // Epilogue: D fragment mapping c0:(g, 2tg) c1:(g, 2tg+1) c2:(g+8, 2tg) c3:(g+8, 2tg+1)
    #pragma unroll
    for (int mt = 0; mt < 2; mt++) {
        int row = bm + wm + mt * 16 + g;
        #pragma unroll
        for (int nt = 0; nt < 8; nt++) {
            int col = bn + wn + nt * 8 + tg * 2;
            float b0 = bias[col], b1 = bias[col + 1];
            C[(size_t)row * N + col]           = acc[mt][nt][0] + b0;
            C[(size_t)row * N + col + 1]       = acc[mt][nt][1] + b1;
            C[(size_t)(row + 8) * N + col]     = acc[mt][nt][2] + b0;
            C[(size_t)(row + 8) * N + col + 1] = acc[mt][nt][3] + b1;
        }
    }
}

// ---------------------------------------------------------------------------
// Flash attention: one block per (b*H + h, 64-query tile).
// 256 threads = 16x16, 4x4 fragment per thread. Parallel online softmax.
// Mask read as 32-bit words, nonzero == keep.
// ---------------------------------------------------------------------------
#define AQ 64
#define AK 64
#define QT_LD 68
#define PS_LD 65

// smem floats: Qt 64*68, Kt 64*68, Vs 64*64, Ps 64*65, m/l/a 3*64, pm 256, psum 256
#define ATTN_SMEM_FLOATS (64*QT_LD*2 + 64*64 + 64*PS_LD + 3*64 + 512)
#define ATTN_SMEM_BYTES  (ATTN_SMEM_FLOATS * 4)

__global__ __launch_bounds__(256, 2)
void attn_kernel(const float* __restrict__ qkv,
                 const unsigned int* __restrict__ mask,
                 float* __restrict__ ao)
{
    extern __shared__ float sm[];
    float* Qt   = sm;                   // [64][68]  Qt[d][q]
    float* Kt   = Qt + 64 * QT_LD;      // [64][68]  Kt[d][k]
    float* Vs   = Kt + 64 * QT_LD;      // [64][64]  Vs[k][d]
    float* Ps   = Vs + 64 * 64;         // [64][65]  scores/probs [q][k]
    float* mrow = Ps + 64 * PS_LD;      // [64]
    float* lrow = mrow + 64;            // [64]
    float* arow = lrow + 64;            // [64]
    float* pm   = arow + 64;            // [4][64] partial max
    float* psum = pm + 256;             // [4][64] partial sum

    const int bh = blockIdx.y;
    const int b  = bh >> 4;
    const int h  = bh & 15;
    const int q0 = blockIdx.x * AQ;
    const int tid = threadIdx.x;
    const int tx = tid & 15;
    const int ty = tid >> 4;
    const int sr = tid & 63;            // softmax row
    const int sq = tid >> 6;            // softmax quarter (0..3)

    const float scale = 0.03125f;                       // 1024^-0.5
    const float slope = exp2f(-0.5f * (float)(h + 1));  // ALiBi slope

    const float* base = qkv + (size_t)b * SEQ * QKVN + h * (3 * DHEAD);

    // Load Q tile (d-major transposed)
    #pragma unroll
    for (int it = 0; it < 4; it++) {
        int idx = tid + it * 256;
        int q   = idx >> 4;
        int d4  = (idx & 15) << 2;
        float4 v = *(const float4*)&base[(size_t)(q0 + q) * QKVN + d4];
        Qt[(d4 + 0) * QT_LD + q] = v.x;
        Qt[(d4 + 1) * QT_LD + q] = v.y;
        Qt[(d4 + 2) * QT_LD + q] = v.z;
        Qt[(d4 + 3) * QT_LD + q] = v.w;
    }
    if (tid < 64) { mrow[tid] = -INFINITY; lrow[tid] = 0.f; }

    float O[4][4];
    #pragma unroll
    for (int i = 0; i < 4; i++)
        #pragma unroll
        for (int j = 0; j < 4; j++) O[i][j] = 0.f;

    __syncthreads();

    for (int k0 = 0; k0 < SEQ; k0 += AK) {
        // Load K (transposed) and V tiles
        #pragma unroll
        for (int it = 0; it < 4; it++) {
            int idx = tid + it * 256;
            int kr  = idx >> 4;
            int d4  = (idx & 15) << 2;
            const float* krow = &base[(size_t)(k0 + kr) * QKVN + DHEAD];
            float4 kv = *(const float4*)&krow[d4];
            Kt[(d4 + 0) * QT_LD + kr] = kv.x;
            Kt[(d4 + 1) * QT_LD + kr] = kv.y;
            Kt[(d4 + 2) * QT_LD + kr] = kv.z;
            Kt[(d4 + 3) * QT_LD + kr] = kv.w;
            float4 vv = *(const float4*)&krow[DHEAD + d4];
            *(float4*)&Vs[kr * 64 + d4] = vv;
        }
        __syncthreads();

        // S = Q @ K^T
        float sc[4][4];
        #pragma unroll
        for (int i = 0; i < 4; i++)
            #pragma unroll
            for (int j = 0; j < 4; j++) sc[i][j] = 0.f;

        #pragma unroll
        for (int kk = 0; kk < 64; kk++) {
            float4 qa = *(float4*)&Qt[kk * QT_LD + ty * 4];
            float4 kb = *(float4*)&Kt[kk * QT_LD + tx * 4];
            float a[4] = {qa.x, qa.y, qa.z, qa.w};
            float bb[4] = {kb.x, kb.y, kb.z, kb.w};
            #pragma unroll
            for (int i = 0; i < 4; i++)
                #pragma unroll
                for (int j = 0; j < 4; j++)
                    sc[i][j] = fmaf(a[i], bb[j], sc[i][j]);
        }

        // scale + ALiBi + mask -> Ps
        #pragma unroll
        for (int i = 0; i < 4; i++) {
            int qg = q0 + ty * 4 + i;
            #pragma unroll
            for (int j = 0; j < 4; j++) {
                int kg = k0 + tx * 4 + j;
                float s = sc[i][j] * scale - slope * fabsf((float)(qg - kg));
                if (mask[b * SEQ + kg] == 0u) s = -3.0e38f;
                Ps[(ty * 4 + i) * PS_LD + tx * 4 + j] = s;
            }
        }
        __syncthreads();

        // --- Parallel online softmax (4 threads per row, 16 elems each) ---
        {
            float tm = -INFINITY;
            const float* prow = &Ps[sr * PS_LD + sq * 16];
            #pragma unroll
            for (int j = 0; j < 16; j++) tm = fmaxf(tm, prow[j]);
            pm[sq * 64 + sr] = tm;
        }
        __syncthreads();
        if (tid < 64) {
            int r = tid;
            float mo = mrow[r];
            float tm = fmaxf(fmaxf(pm[r], pm[64 + r]), fmaxf(pm[128 + r], pm[192 + r]));
            float mn = fmaxf(mo, tm);
            arow[r] = __expf(mo - mn);
            mrow[r] = mn;
        }
        __syncthreads();
        {
            float mn = mrow[sr];
            float* prow = &Ps[sr * PS_LD + sq * 16];
            float sum = 0.f;
            #pragma unroll
            for (int j = 0; j < 16; j++) {
                float p = __expf(prow[j] - mn);
                prow[j] = p;
                sum += p;
            }
            psum[sq * 64 + sr] = sum;
        }
        __syncthreads();
        if (tid < 64) {
            int r = tid;
            lrow[r] = lrow[r] * arow[r] +
                      (psum[r] + psum[64 + r]) + (psum[128 + r] + psum[192 + r]);
        }

        // O = O*alpha + P @ V   (arow/Ps ready; no extra sync needed before reads)
        float ai[4];
        #pragma unroll
        for (int i = 0; i < 4; i++) ai[i] = arow[ty * 4 + i];
        #pragma unroll
        for (int i = 0; i < 4; i++)
            #pragma unroll
            for (int j = 0; j < 4; j++) O[i][j] *= ai[i];

        #pragma unroll
        for (int kk = 0; kk < 64; kk++) {
            float p[4];
            #pragma unroll
            for (int i = 0; i < 4; i++) p[i] = Ps[(ty * 4 + i) * PS_LD + kk];
            float4 vv = *(float4*)&Vs[kk * 64 + tx * 4];
            float vj[4] = {vv.x, vv.y, vv.z, vv.w};
            #pragma unroll
            for (int i = 0; i < 4; i++)
                #pragma unroll
                for (int j = 0; j < 4; j++)
                    O[i][j] = fmaf(p[i], vj[j], O[i][j]);
        }
        __syncthreads();
    }

    // Finalize
    float linv[4];
    #pragma unroll
    for (int i = 0; i < 4; i++) linv[i] = 1.f / lrow[ty * 4 + i];
    #pragma unroll
    for (int i = 0; i < 4; i++) {
        int sg = q0 + ty * 4 + i;
        #pragma unroll
        for (int j = 0; j < 4; j++) {
            int d = tx * 4 + j;
            ao[((size_t)(b * SEQ + sg)) * DMODEL + h * DHEAD + d] = O[i][j] * linv[i];
        }
    }
}

// ---------------------------------------------------------------------------
extern "C" void kernel_launch(void* const* d_in, const int* in_sizes, int n_in,
                              void* d_out, int out_size)
{
    const float* X     = (const float*)d_in[0];
    const unsigned int* mask = (const unsigned int*)d_in[1];
    const float* Wqkv  = (const float*)d_in[2];
    const float* bqkv  = (const float*)d_in[3];
    const float* Wproj = (const float*)d_in[4];
    const float* bproj = (const float*)d_in[5];
    float* out = (float*)d_out;

    float *qkv, *ao;
    cudaGetSymbolAddress((void**)&qkv, g_qkv);
    cudaGetSymbolAddress((void**)&ao,  g_ao);

    cudaFuncSetAttribute(attn_kernel, cudaFuncAttributeMaxDynamicSharedMemorySize,
                         ATTN_SMEM_BYTES);

    // 1) QKV projection: [4096,1024] @ [3072,1024]^T -> [4096,3072]
    sgemm_tf32<<<dim3(QKVN / 128, NTOK / 128), 256>>>(X, Wqkv, bqkv, qkv,
                                                      NTOK, QKVN, DMODEL);
    // 2) Flash attention
    attn_kernel<<<dim3(SEQ / AQ, BATCH * NHEAD), 256, ATTN_SMEM_BYTES>>>(qkv, mask, ao);
    // 3) Output projection: [4096,1024] @ [1024,1024]^T -> [4096,1024]
    sgemm_tf32<<<dim3(DMODEL / 128, NTOK / 128), 256>>>(ao, Wproj, bproj, out,
                                                        NTOK, DMODEL, DMODEL);
}

// round 5
// speedup vs baseline: 2.7369x; 1.7564x over previous
#include <cuda_runtime.h>
#include <math.h>
#include <stdint.h>

// Problem constants
#define BATCH 2
#define SEQ   2048
#define DMODEL 1024
#define NHEAD 16
#define DHEAD 64
#define NTOK  (BATCH*SEQ)          // 4096
#define QKVN  (3*DMODEL)           // 3072

// Scratch (allocation-free rule: __device__ globals)
__device__ float g_qkv[(size_t)NTOK * QKVN];   // [4096][3072]
__device__ float g_ao [(size_t)NTOK * DMODEL]; // [4096][1024]

__device__ __forceinline__ uint32_t f2tf32(float f) {
    uint32_t u;
    asm("cvt.rna.tf32.f32 %0, %1;" : "=r"(u) : "f"(f));
    return u;
}

__device__ __forceinline__ void mma_tf32(float c[4], const uint32_t a[4], const uint32_t b[2]) {
    asm volatile(
        "mma.sync.aligned.m16n8k8.row.col.f32.tf32.tf32.f32 "
        "{%0,%1,%2,%3}, {%4,%5,%6,%7}, {%8,%9}, {%0,%1,%2,%3};"
        : "+f"(c[0]), "+f"(c[1]), "+f"(c[2]), "+f"(c[3])
        : "r"(a[0]), "r"(a[1]), "r"(a[2]), "r"(a[3]), "r"(b[0]), "r"(b[1]));
}

// ---------------------------------------------------------------------------
// TF32 tensor-core GEMM: C[M,N] = A[M,K] @ W[N,K]^T + bias[N]
// 128x128 block tile, BK=32, 256 threads = 8 warps (4x2), warp tile 32x64.
// ---------------------------------------------------------------------------
#define GLD 36

__global__ __launch_bounds__(256, 2)
void sgemm_tf32(const float* __restrict__ A, const float* __restrict__ W,
                const float* __restrict__ bias, float* __restrict__ C,
                int M, int N, int K)
{
    __shared__ uint32_t As[128][GLD];
    __shared__ uint32_t Ws[128][GLD];

    const int tid = threadIdx.x;
    const int l   = tid & 31;
    const int w   = tid >> 5;
    const int wm  = (w & 3) * 32;
    const int wn  = (w >> 2) * 64;
    const int bm  = blockIdx.y * 128;
    const int bn  = blockIdx.x * 128;
    const int g   = l >> 2;
    const int tg  = l & 3;

    float acc[2][8][4];
    #pragma unroll
    for (int i = 0; i < 2; i++)
        #pragma unroll
        for (int j = 0; j < 8; j++)
            #pragma unroll
            for (int t = 0; t < 4; t++) acc[i][j][t] = 0.f;

    for (int k0 = 0; k0 < K; k0 += 32) {
        #pragma unroll
        for (int it = 0; it < 4; it++) {
            int idx = tid + it * 256;
            int row = idx >> 3;
            int kq  = (idx & 7) << 2;
            float4 va = *(const float4*)&A[(size_t)(bm + row) * K + k0 + kq];
            uint4 ua = make_uint4(f2tf32(va.x), f2tf32(va.y), f2tf32(va.z), f2tf32(va.w));
            *(uint4*)&As[row][kq] = ua;
            float4 vb = *(const float4*)&W[(size_t)(bn + row) * K + k0 + kq];
            uint4 ub = make_uint4(f2tf32(vb.x), f2tf32(vb.y), f2tf32(vb.z), f2tf32(vb.w));
            *(uint4*)&Ws[row][kq] = ub;
        }
        __syncthreads();

        #pragma unroll
        for (int ks = 0; ks < 4; ks++) {
            int k8 = ks * 8;
            uint32_t af[2][4];
            #pragma unroll
            for (int mt = 0; mt < 2; mt++) {
                int r0 = wm + mt * 16 + g;
                af[mt][0] = As[r0    ][k8 + tg];
                af[mt][1] = As[r0 + 8][k8 + tg];
                af[mt][2] = As[r0    ][k8 + 4 + tg];
                af[mt][3] = As[r0 + 8][k8 + 4 + tg];
            }
            uint32_t bf[8][2];
            #pragma unroll
            for (int nt = 0; nt < 8; nt++) {
                int c0 = wn + nt * 8 + g;
                bf[nt][0] = Ws[c0][k8 + tg];
                bf[nt][1] = Ws[c0][k8 + 4 + tg];
            }
            #pragma unroll
            for (int mt = 0; mt < 2; mt++)
                #pragma unroll
                for (int nt = 0; nt < 8; nt++)
                    mma_tf32(acc[mt][nt], af[mt], bf[nt]);
        }
        __syncthreads();
    }

    #pragma unroll
    for (int mt = 0; mt < 2; mt++) {
        int row = bm + wm + mt * 16 + g;
        #pragma unroll
        for (int nt = 0; nt < 8; nt++) {
            int col = bn + wn + nt * 8 + tg * 2;
            float b0 = bias[col], b1 = bias[col + 1];
            C[(size_t)row * N + col]           = acc[mt][nt][0] + b0;
            C[(size_t)row * N + col + 1]       = acc[mt][nt][1] + b1;
            C[(size_t)(row + 8) * N + col]     = acc[mt][nt][2] + b0;
            C[(size_t)(row + 8) * N + col + 1] = acc[mt][nt][3] + b1;
        }
    }
}

// ---------------------------------------------------------------------------
// Tensor-core flash attention.
// Block: 256 threads = 8 warps. Tile: 128 queries x 64 keys, dh = 64.
// Warp w owns query rows [w*16, w*16+16). Q fragments register-resident
// (pre-scaled by 1/32). Online softmax in registers with quad shuffles.
// P -> smem (reuses dead Q region) -> A-fragments for PV mma.
// ---------------------------------------------------------------------------
#define BQ 128
#define BK 64
#define APAD 68

// words: Qs/Ps 128*68, Ks 64*68, Vt 64*68, mask 64
#define ATTN_SMEM_WORDS (128*APAD + 64*APAD + 64*APAD + 64)
#define ATTN_SMEM_BYTES (ATTN_SMEM_WORDS * 4)

__global__ __launch_bounds__(256, 1)
void attn_mma(const float* __restrict__ qkv,
              const unsigned int* __restrict__ mask,
              float* __restrict__ ao)
{
    extern __shared__ uint32_t smw[];
    uint32_t* Qs = smw;                    // [128][APAD]; becomes Ps after Q frags read
    uint32_t* Ks = smw + 128 * APAD;       // [64][APAD]  K[key][d] tf32
    uint32_t* Vt = Ks + 64 * APAD;         // [64][APAD]  V^T: Vt[d][key] tf32
    float* maskadd = (float*)(Vt + 64 * APAD); // [64]

    const int bh = blockIdx.y;
    const int b  = bh >> 4;
    const int h  = bh & 15;
    const int q0 = blockIdx.x * BQ;
    const int tid = threadIdx.x;
    const int w  = tid >> 5;
    const int l  = tid & 31;
    const int g  = l >> 2;
    const int tg = l & 3;
    const int r0 = w * 16 + g;             // warp-local A-frag row

    const float scale = 0.03125f;
    const float slope = exp2f(-0.5f * (float)(h + 1));
    const float* base = qkv + (size_t)b * SEQ * QKVN + h * (3 * DHEAD);

    // --- Load Q tile (scaled, tf32) ---
    #pragma unroll
    for (int it = 0; it < 8; it++) {
        int idx = tid + it * 256;          // 2048 float4 slots
        int row = idx >> 4;
        int d4  = (idx & 15) << 2;
        float4 v = *(const float4*)&base[(size_t)(q0 + row) * QKVN + d4];
        uint4 u = make_uint4(f2tf32(v.x * scale), f2tf32(v.y * scale),
                             f2tf32(v.z * scale), f2tf32(v.w * scale));
        *(uint4*)&Qs[row * APAD + d4] = u;
    }
    __syncthreads();

    // --- Q fragments, register resident (8 k-slices x 4 regs) ---
    uint32_t qa[8][4];
    #pragma unroll
    for (int ks = 0; ks < 8; ks++) {
        int k8 = ks * 8;
        qa[ks][0] = Qs[r0 * APAD + k8 + tg];
        qa[ks][1] = Qs[(r0 + 8) * APAD + k8 + tg];
        qa[ks][2] = Qs[r0 * APAD + k8 + 4 + tg];
        qa[ks][3] = Qs[(r0 + 8) * APAD + k8 + 4 + tg];
    }
    __syncthreads();                       // Qs now dead -> reuse as Ps
    uint32_t* Ps = Qs;

    float o[8][4];
    #pragma unroll
    for (int nt = 0; nt < 8; nt++)
        #pragma unroll
        for (int c = 0; c < 4; c++) o[nt][c] = 0.f;
    float m0 = -INFINITY, m1 = -INFINITY, l0 = 0.f, l1 = 0.f;

    const int qg0 = q0 + r0;
    const int qg1 = qg0 + 8;

    for (int k0 = 0; k0 < SEQ; k0 += BK) {
        // --- Load K (row-major) and V (transposed) tiles, tf32 ---
        #pragma unroll
        for (int it = 0; it < 4; it++) {
            int idx = tid + it * 256;      // 1024 float4 slots
            int kr  = idx >> 4;
            int d4  = (idx & 15) << 2;
            const float* kp = &base[(size_t)(k0 + kr) * QKVN + DHEAD];
            float4 kv = *(const float4*)&kp[d4];
            uint4 uk = make_uint4(f2tf32(kv.x), f2tf32(kv.y), f2tf32(kv.z), f2tf32(kv.w));
            *(uint4*)&Ks[kr * APAD + d4] = uk;
            float4 vv = *(const float4*)&kp[DHEAD + d4];
            Vt[(d4 + 0) * APAD + kr] = f2tf32(vv.x);
            Vt[(d4 + 1) * APAD + kr] = f2tf32(vv.y);
            Vt[(d4 + 2) * APAD + kr] = f2tf32(vv.z);
            Vt[(d4 + 3) * APAD + kr] = f2tf32(vv.w);
        }
        if (tid < 64)
            maskadd[tid] = mask[b * SEQ + k0 + tid] ? 0.f : -3.0e38f;
        __syncthreads();

        // --- S = Qs @ K^T ---
        float s[8][4];
        #pragma unroll
        for (int nt = 0; nt < 8; nt++)
            #pragma unroll
            for (int c = 0; c < 4; c++) s[nt][c] = 0.f;

        #pragma unroll
        for (int ks = 0; ks < 8; ks++) {
            int k8 = ks * 8;
            uint32_t bf[8][2];
            #pragma unroll
            for (int nt = 0; nt < 8; nt++) {
                int c0 = nt * 8 + g;
                bf[nt][0] = Ks[c0 * APAD + k8 + tg];
                bf[nt][1] = Ks[c0 * APAD + k8 + 4 + tg];
            }
            #pragma unroll
            for (int nt = 0; nt < 8; nt++)
                mma_tf32(s[nt], qa[ks], bf[nt]);
        }

        // --- ALiBi + mask, tile row max ---
        float mx0 = -INFINITY, mx1 = -INFINITY;
        #pragma unroll
        for (int nt = 0; nt < 8; nt++) {
            int lc0 = nt * 8 + 2 * tg;
            int kg0 = k0 + lc0, kg1 = kg0 + 1;
            float ma0 = maskadd[lc0], ma1 = maskadd[lc0 + 1];
            s[nt][0] += ma0 - slope * fabsf((float)(qg0 - kg0));
            s[nt][1] += ma1 - slope * fabsf((float)(qg0 - kg1));
            s[nt][2] += ma0 - slope * fabsf((float)(qg1 - kg0));
            s[nt][3] += ma1 - slope * fabsf((float)(qg1 - kg1));
            mx0 = fmaxf(mx0, fmaxf(s[nt][0], s[nt][1]));
            mx1 = fmaxf(mx1, fmaxf(s[nt][2], s[nt][3]));
        }
        mx0 = fmaxf(mx0, __shfl_xor_sync(0xffffffffu, mx0, 1));
        mx0 = fmaxf(mx0, __shfl_xor_sync(0xffffffffu, mx0, 2));
        mx1 = fmaxf(mx1, __shfl_xor_sync(0xffffffffu, mx1, 1));
        mx1 = fmaxf(mx1, __shfl_xor_sync(0xffffffffu, mx1, 2));

        float mn0 = fmaxf(m0, mx0), mn1 = fmaxf(m1, mx1);
        float al0 = __expf(m0 - mn0), al1 = __expf(m1 - mn1);
        m0 = mn0; m1 = mn1;

        // --- exp, row sums, store P (tf32) ---
        float sum0 = 0.f, sum1 = 0.f;
        #pragma unroll
        for (int nt = 0; nt < 8; nt++) {
            float p00 = __expf(s[nt][0] - mn0);
            float p01 = __expf(s[nt][1] - mn0);
            float p10 = __expf(s[nt][2] - mn1);
            float p11 = __expf(s[nt][3] - mn1);
            sum0 += p00 + p01;
            sum1 += p10 + p11;
            int lc = nt * 8 + 2 * tg;
            *(uint2*)&Ps[r0 * APAD + lc]       = make_uint2(f2tf32(p00), f2tf32(p01));
            *(uint2*)&Ps[(r0 + 8) * APAD + lc] = make_uint2(f2tf32(p10), f2tf32(p11));
        }
        sum0 += __shfl_xor_sync(0xffffffffu, sum0, 1);
        sum0 += __shfl_xor_sync(0xffffffffu, sum0, 2);
        sum1 += __shfl_xor_sync(0xffffffffu, sum1, 1);
        sum1 += __shfl_xor_sync(0xffffffffu, sum1, 2);
        l0 = l0 * al0 + sum0;
        l1 = l1 * al1 + sum1;

        // --- Rescale O ---
        #pragma unroll
        for (int nt = 0; nt < 8; nt++) {
            o[nt][0] *= al0; o[nt][1] *= al0;
            o[nt][2] *= al1; o[nt][3] *= al1;
        }
        __syncwarp();                      // P rows are warp-private

        // --- O += P @ V ---
        #pragma unroll
        for (int ks = 0; ks < 8; ks++) {
            int k8 = ks * 8;
            uint32_t pa[4];
            pa[0] = Ps[r0 * APAD + k8 + tg];
            pa[1] = Ps[(r0 + 8) * APAD + k8 + tg];
            pa[2] = Ps[r0 * APAD + k8 + 4 + tg];
            pa[3] = Ps[(r0 + 8) * APAD + k8 + 4 + tg];
            uint32_t vf[8][2];
            #pragma unroll
            for (int nt = 0; nt < 8; nt++) {
                int c0 = nt * 8 + g;
                vf[nt][0] = Vt[c0 * APAD + k8 + tg];
                vf[nt][1] = Vt[c0 * APAD + k8 + 4 + tg];
            }
            #pragma unroll
            for (int nt = 0; nt < 8; nt++)
                mma_tf32(o[nt], pa, vf[nt]);
        }
        __syncthreads();                   // before next tile overwrites Ks/Vt
    }

    // --- Finalize ---
    float il0 = 1.f / l0, il1 = 1.f / l1;
    #pragma unroll
    for (int nt = 0; nt < 8; nt++) {
        int col = h * DHEAD + nt * 8 + 2 * tg;
        float2 v0 = make_float2(o[nt][0] * il0, o[nt][1] * il0);
        float2 v1 = make_float2(o[nt][2] * il1, o[nt][3] * il1);
        *(float2*)&ao[(size_t)(b * SEQ + qg0) * DMODEL + col] = v0;
        *(float2*)&ao[(size_t)(b * SEQ + qg1) * DMODEL + col] = v1;
    }
}

// ---------------------------------------------------------------------------
extern "C" void kernel_launch(void* const* d_in, const int* in_sizes, int n_in,
                              void* d_out, int out_size)
{
    const float* X     = (const float*)d_in[0];
    const unsigned int* mask = (const unsigned int*)d_in[1];
    const float* Wqkv  = (const float*)d_in[2];
    const float* bqkv  = (const float*)d_in[3];
    const float* Wproj = (const float*)d_in[4];
    const float* bproj = (const float*)d_in[5];
    float* out = (float*)d_out;

    float *qkv, *ao;
    cudaGetSymbolAddress((void**)&qkv, g_qkv);
    cudaGetSymbolAddress((void**)&ao,  g_ao);

    cudaFuncSetAttribute(attn_mma, cudaFuncAttributeMaxDynamicSharedMemorySize,
                         ATTN_SMEM_BYTES);

    // 1) QKV projection
    sgemm_tf32<<<dim3(QKVN / 128, NTOK / 128), 256>>>(X, Wqkv, bqkv, qkv,
                                                      NTOK, QKVN, DMODEL);
    // 2) Flash attention (tensor cores)
    attn_mma<<<dim3(SEQ / BQ, BATCH * NHEAD), 256, ATTN_SMEM_BYTES>>>(qkv, mask, ao);
    // 3) Output projection
    sgemm_tf32<<<dim3(DMODEL / 128, NTOK / 128), 256>>>(ao, Wproj, bproj, out,
                                                        NTOK, DMODEL, DMODEL);
}

// round 6
// speedup vs baseline: 2.9849x; 1.0906x over previous
#include <cuda_runtime.h>
#include <math.h>
#include <stdint.h>

// Problem constants
#define BATCH 2
#define SEQ   2048
#define DMODEL 1024
#define NHEAD 16
#define DHEAD 64
#define NTOK  (BATCH*SEQ)          // 4096
#define QKVN  (3*DMODEL)           // 3072

// Scratch (allocation-free rule: __device__ globals)
__device__ float g_qkv[(size_t)NTOK * QKVN];   // [4096][3072]
__device__ float g_ao [(size_t)NTOK * DMODEL]; // [4096][1024]

__device__ __forceinline__ uint32_t f2tf32(float f) {
    uint32_t u;
    asm("cvt.rna.tf32.f32 %0, %1;" : "=r"(u) : "f"(f));
    return u;
}

__device__ __forceinline__ void mma_tf32(float c[4], const uint32_t a[4], const uint32_t b[2]) {
    asm volatile(
        "mma.sync.aligned.m16n8k8.row.col.f32.tf32.tf32.f32 "
        "{%0,%1,%2,%3}, {%4,%5,%6,%7}, {%8,%9}, {%0,%1,%2,%3};"
        : "+f"(c[0]), "+f"(c[1]), "+f"(c[2]), "+f"(c[3])
        : "r"(a[0]), "r"(a[1]), "r"(a[2]), "r"(a[3]), "r"(b[0]), "r"(b[1]));
}

__device__ __forceinline__ void cp_async16(uint32_t smem_addr, const void* gptr) {
    asm volatile("cp.async.ca.shared.global [%0], [%1], 16;\n"
                 :: "r"(smem_addr), "l"(gptr));
}
__device__ __forceinline__ void cp_commit() {
    asm volatile("cp.async.commit_group;\n");
}
__device__ __forceinline__ void cp_wait0() {
    asm volatile("cp.async.wait_group 0;\n");
}

// ---------------------------------------------------------------------------
// TF32 tensor-core GEMM with cp.async double buffering.
// C[M,N] = A[M,K] @ W[N,K]^T + bias[N]
// 128x128 block tile, BK=32, 256 threads = 8 warps (4x2), warp tile 32x64.
// Smem holds RAW fp32; tf32 conversion (RNA) happens at fragment load.
// ---------------------------------------------------------------------------
#define GLD 36
#define SG_STAGE (128*GLD)                 // words per matrix per stage
#define SGEMM_SMEM_BYTES (4*SG_STAGE*4)    // A[2] + W[2]

__global__ __launch_bounds__(256, 2)
void sgemm_tf32(const float* __restrict__ A, const float* __restrict__ W,
                const float* __restrict__ bias, float* __restrict__ C,
                int M, int N, int K)
{
    extern __shared__ uint32_t sgs[];
    uint32_t* As = sgs;                    // [2][128][GLD] raw fp32 bits
    uint32_t* Ws = sgs + 2 * SG_STAGE;     // [2][128][GLD]

    const int tid = threadIdx.x;
    const int l   = tid & 31;
    const int w   = tid >> 5;
    const int wm  = (w & 3) * 32;
    const int wn  = (w >> 2) * 64;
    const int bm  = blockIdx.y * 128;
    const int bn  = blockIdx.x * 128;
    const int g   = l >> 2;
    const int tg  = l & 3;

    const int KT = K >> 5;                 // k-tile count

    float acc[2][8][4];
    #pragma unroll
    for (int i = 0; i < 2; i++)
        #pragma unroll
        for (int j = 0; j < 8; j++)
            #pragma unroll
            for (int t = 0; t < 4; t++) acc[i][j][t] = 0.f;

    // Per-thread load coordinates (4 float4 per matrix per stage)
    // idx = tid + it*256 ; row = idx>>3 ; kq = (idx&7)<<2
    auto issue_stage = [&](int kt, int buf) {
        int k0 = kt << 5;
        #pragma unroll
        for (int it = 0; it < 4; it++) {
            int idx = tid + it * 256;
            int row = idx >> 3;
            int kq  = (idx & 7) << 2;
            uint32_t da = (uint32_t)__cvta_generic_to_shared(
                &As[buf * SG_STAGE + row * GLD + kq]);
            cp_async16(da, &A[(size_t)(bm + row) * K + k0 + kq]);
            uint32_t dw = (uint32_t)__cvta_generic_to_shared(
                &Ws[buf * SG_STAGE + row * GLD + kq]);
            cp_async16(dw, &W[(size_t)(bn + row) * K + k0 + kq]);
        }
        cp_commit();
    };

    issue_stage(0, 0);

    for (int kt = 0; kt < KT; kt++) {
        cp_wait0();
        __syncthreads();                   // stage kt visible to all; prev compute done
        if (kt + 1 < KT) issue_stage(kt + 1, (kt + 1) & 1);

        const uint32_t* Ab = &As[(kt & 1) * SG_STAGE];
        const uint32_t* Wb = &Ws[(kt & 1) * SG_STAGE];

        #pragma unroll
        for (int ks = 0; ks < 4; ks++) {
            int k8 = ks * 8;
            uint32_t af[2][4];
            #pragma unroll
            for (int mt = 0; mt < 2; mt++) {
                int r0 = wm + mt * 16 + g;
                af[mt][0] = f2tf32(__uint_as_float(Ab[r0 * GLD + k8 + tg]));
                af[mt][1] = f2tf32(__uint_as_float(Ab[(r0 + 8) * GLD + k8 + tg]));
                af[mt][2] = f2tf32(__uint_as_float(Ab[r0 * GLD + k8 + 4 + tg]));
                af[mt][3] = f2tf32(__uint_as_float(Ab[(r0 + 8) * GLD + k8 + 4 + tg]));
            }
            uint32_t bf[8][2];
            #pragma unroll
            for (int nt = 0; nt < 8; nt++) {
                int c0 = wn + nt * 8 + g;
                bf[nt][0] = f2tf32(__uint_as_float(Wb[c0 * GLD + k8 + tg]));
                bf[nt][1] = f2tf32(__uint_as_float(Wb[c0 * GLD + k8 + 4 + tg]));
            }
            #pragma unroll
            for (int mt = 0; mt < 2; mt++)
                #pragma unroll
                for (int nt = 0; nt < 8; nt++)
                    mma_tf32(acc[mt][nt], af[mt], bf[nt]);
        }
        __syncthreads();                   // compute done before buffer reuse
    }

    #pragma unroll
    for (int mt = 0; mt < 2; mt++) {
        int row = bm + wm + mt * 16 + g;
        #pragma unroll
        for (int nt = 0; nt < 8; nt++) {
            int col = bn + wn + nt * 8 + tg * 2;
            float b0 = bias[col], b1 = bias[col + 1];
            C[(size_t)row * N + col]           = acc[mt][nt][0] + b0;
            C[(size_t)row * N + col + 1]       = acc[mt][nt][1] + b1;
            C[(size_t)(row + 8) * N + col]     = acc[mt][nt][2] + b0;
            C[(size_t)(row + 8) * N + col + 1] = acc[mt][nt][3] + b1;
        }
    }
}

// ---------------------------------------------------------------------------
// Tensor-core flash attention. 2 CTAs/SM for latency hiding.
// Block: 256 threads = 8 warps. Tile: 128 queries x 64 keys, dh = 64.
// ---------------------------------------------------------------------------
#define BQ 128
#define BK 64
#define APAD 68

// words: Qs/Ps 128*68, Ks 64*68, Vt 64*68, mask 64
#define ATTN_SMEM_WORDS (128*APAD + 64*APAD + 64*APAD + 64)
#define ATTN_SMEM_BYTES (ATTN_SMEM_WORDS * 4)

__global__ __launch_bounds__(256, 2)
void attn_mma(const float* __restrict__ qkv,
              const unsigned int* __restrict__ mask,
              float* __restrict__ ao)
{
    extern __shared__ uint32_t smw[];
    uint32_t* Qs = smw;                    // [128][APAD]; becomes Ps after Q frags read
    uint32_t* Ks = smw + 128 * APAD;       // [64][APAD]  K[key][d] tf32
    uint32_t* Vt = Ks + 64 * APAD;         // [64][APAD]  V^T: Vt[d][key] tf32
    float* maskadd = (float*)(Vt + 64 * APAD); // [64]

    const int bh = blockIdx.y;
    const int b  = bh >> 4;
    const int h  = bh & 15;
    const int q0 = blockIdx.x * BQ;
    const int tid = threadIdx.x;
    const int w  = tid >> 5;
    const int l  = tid & 31;
    const int g  = l >> 2;
    const int tg = l & 3;
    const int r0 = w * 16 + g;             // warp-local A-frag row

    const float scale = 0.03125f;
    const float slope = exp2f(-0.5f * (float)(h + 1));
    const float* base = qkv + (size_t)b * SEQ * QKVN + h * (3 * DHEAD);

    // --- Load Q tile (scaled, tf32) ---
    #pragma unroll
    for (int it = 0; it < 8; it++) {
        int idx = tid + it * 256;          // 2048 float4 slots
        int row = idx >> 4;
        int d4  = (idx & 15) << 2;
        float4 v = *(const float4*)&base[(size_t)(q0 + row) * QKVN + d4];
        uint4 u = make_uint4(f2tf32(v.x * scale), f2tf32(v.y * scale),
                             f2tf32(v.z * scale), f2tf32(v.w * scale));
        *(uint4*)&Qs[row * APAD + d4] = u;
    }
    __syncthreads();

    // --- Q fragments, register resident (8 k-slices x 4 regs) ---
    uint32_t qa[8][4];
    #pragma unroll
    for (int ks = 0; ks < 8; ks++) {
        int k8 = ks * 8;
        qa[ks][0] = Qs[r0 * APAD + k8 + tg];
        qa[ks][1] = Qs[(r0 + 8) * APAD + k8 + tg];
        qa[ks][2] = Qs[r0 * APAD + k8 + 4 + tg];
        qa[ks][3] = Qs[(r0 + 8) * APAD + k8 + 4 + tg];
    }
    __syncthreads();                       // Qs now dead -> reuse as Ps
    uint32_t* Ps = Qs;

    float o[8][4];
    #pragma unroll
    for (int nt = 0; nt < 8; nt++)
        #pragma unroll
        for (int c = 0; c < 4; c++) o[nt][c] = 0.f;
    float m0 = -INFINITY, m1 = -INFINITY, l0 = 0.f, l1 = 0.f;

    const int qg0 = q0 + r0;
    const int qg1 = qg0 + 8;

    for (int k0 = 0; k0 < SEQ; k0 += BK) {
        // --- Load K (row-major) and V (transposed) tiles, tf32 ---
        #pragma unroll
        for (int it = 0; it < 4; it++) {
            int idx = tid + it * 256;      // 1024 float4 slots
            int kr  = idx >> 4;
            int d4  = (idx & 15) << 2;
            const float* kp = &base[(size_t)(k0 + kr) * QKVN + DHEAD];
            float4 kv = *(const float4*)&kp[d4];
            uint4 uk = make_uint4(f2tf32(kv.x), f2tf32(kv.y), f2tf32(kv.z), f2tf32(kv.w));
            *(uint4*)&Ks[kr * APAD + d4] = uk;
            float4 vv = *(const float4*)&kp[DHEAD + d4];
            Vt[(d4 + 0) * APAD + kr] = f2tf32(vv.x);
            Vt[(d4 + 1) * APAD + kr] = f2tf32(vv.y);
            Vt[(d4 + 2) * APAD + kr] = f2tf32(vv.z);
            Vt[(d4 + 3) * APAD + kr] = f2tf32(vv.w);
        }
        if (tid < 64)
            maskadd[tid] = mask[b * SEQ + k0 + tid] ? 0.f : -3.0e38f;
        __syncthreads();

        // --- S = Qs @ K^T ---
        float s[8][4];
        #pragma unroll
        for (int nt = 0; nt < 8; nt++)
            #pragma unroll
            for (int c = 0; c < 4; c++) s[nt][c] = 0.f;

        #pragma unroll
        for (int ks = 0; ks < 8; ks++) {
            int k8 = ks * 8;
            uint32_t bf[8][2];
            #pragma unroll
            for (int nt = 0; nt < 8; nt++) {
                int c0 = nt * 8 + g;
                bf[nt][0] = Ks[c0 * APAD + k8 + tg];
                bf[nt][1] = Ks[c0 * APAD + k8 + 4 + tg];
            }
            #pragma unroll
            for (int nt = 0; nt < 8; nt++)
                mma_tf32(s[nt], qa[ks], bf[nt]);
        }

        // --- ALiBi + mask, tile row max ---
        float mx0 = -INFINITY, mx1 = -INFINITY;
        #pragma unroll
        for (int nt = 0; nt < 8; nt++) {
            int lc0 = nt * 8 + 2 * tg;
            int kg0 = k0 + lc0, kg1 = kg0 + 1;
            float ma0 = maskadd[lc0], ma1 = maskadd[lc0 + 1];
            s[nt][0] += ma0 - slope * fabsf((float)(qg0 - kg0));
            s[nt][1] += ma1 - slope * fabsf((float)(qg0 - kg1));
            s[nt][2] += ma0 - slope * fabsf((float)(qg1 - kg0));
            s[nt][3] += ma1 - slope * fabsf((float)(qg1 - kg1));
            mx0 = fmaxf(mx0, fmaxf(s[nt][0], s[nt][1]));
            mx1 = fmaxf(mx1, fmaxf(s[nt][2], s[nt][3]));
        }
        mx0 = fmaxf(mx0, __shfl_xor_sync(0xffffffffu, mx0, 1));
        mx0 = fmaxf(mx0, __shfl_xor_sync(0xffffffffu, mx0, 2));
        mx1 = fmaxf(mx1, __shfl_xor_sync(0xffffffffu, mx1, 1));
        mx1 = fmaxf(mx1, __shfl_xor_sync(0xffffffffu, mx1, 2));

        float mn0 = fmaxf(m0, mx0), mn1 = fmaxf(m1, mx1);
        float al0 = __expf(m0 - mn0), al1 = __expf(m1 - mn1);
        m0 = mn0; m1 = mn1;

        // --- exp, row sums, store P (tf32) ---
        float sum0 = 0.f, sum1 = 0.f;
        #pragma unroll
        for (int nt = 0; nt < 8; nt++) {
            float p00 = __expf(s[nt][0] - mn0);
            float p01 = __expf(s[nt][1] - mn0);
            float p10 = __expf(s[nt][2] - mn1);
            float p11 = __expf(s[nt][3] - mn1);
            sum0 += p00 + p01;
            sum1 += p10 + p11;
            int lc = nt * 8 + 2 * tg;
            *(uint2*)&Ps[r0 * APAD + lc]       = make_uint2(f2tf32(p00), f2tf32(p01));
            *(uint2*)&Ps[(r0 + 8) * APAD + lc] = make_uint2(f2tf32(p10), f2tf32(p11));
        }
        sum0 += __shfl_xor_sync(0xffffffffu, sum0, 1);
        sum0 += __shfl_xor_sync(0xffffffffu, sum0, 2);
        sum1 += __shfl_xor_sync(0xffffffffu, sum1, 1);
        sum1 += __shfl_xor_sync(0xffffffffu, sum1, 2);
        l0 = l0 * al0 + sum0;
        l1 = l1 * al1 + sum1;

        // --- Rescale O ---
        #pragma unroll
        for (int nt = 0; nt < 8; nt++) {
            o[nt][0] *= al0; o[nt][1] *= al0;
            o[nt][2] *= al1; o[nt][3] *= al1;
        }
        __syncwarp();                      // P rows are warp-private

        // --- O += P @ V ---
        #pragma unroll
        for (int ks = 0; ks < 8; ks++) {
            int k8 = ks * 8;
            uint32_t pa[4];
            pa[0] = Ps[r0 * APAD + k8 + tg];
            pa[1] = Ps[(r0 + 8) * APAD + k8 + tg];
            pa[2] = Ps[r0 * APAD + k8 + 4 + tg];
            pa[3] = Ps[(r0 + 8) * APAD + k8 + 4 + tg];
            uint32_t vf[8][2];
            #pragma unroll
            for (int nt = 0; nt < 8; nt++) {
                int c0 = nt * 8 + g;
                vf[nt][0] = Vt[c0 * APAD + k8 + tg];
                vf[nt][1] = Vt[c0 * APAD + k8 + 4 + tg];
            }
            #pragma unroll
            for (int nt = 0; nt < 8; nt++)
                mma_tf32(o[nt], pa, vf[nt]);
        }
        __syncthreads();                   // before next tile overwrites Ks/Vt
    }

    // --- Finalize ---
    float il0 = 1.f / l0, il1 = 1.f / l1;
    #pragma unroll
    for (int nt = 0; nt < 8; nt++) {
        int col = h * DHEAD + nt * 8 + 2 * tg;
        float2 v0 = make_float2(o[nt][0] * il0, o[nt][1] * il0);
        float2 v1 = make_float2(o[nt][2] * il1, o[nt][3] * il1);
        *(float2*)&ao[(size_t)(b * SEQ + qg0) * DMODEL + col] = v0;
        *(float2*)&ao[(size_t)(b * SEQ + qg1) * DMODEL + col] = v1;
    }
}

// ---------------------------------------------------------------------------
extern "C" void kernel_launch(void* const* d_in, const int* in_sizes, int n_in,
                              void* d_out, int out_size)
{
    const float* X     = (const float*)d_in[0];
    const unsigned int* mask = (const unsigned int*)d_in[1];
    const float* Wqkv  = (const float*)d_in[2];
    const float* bqkv  = (const float*)d_in[3];
    const float* Wproj = (const float*)d_in[4];
    const float* bproj = (const float*)d_in[5];
    float* out = (float*)d_out;

    float *qkv, *ao;
    cudaGetSymbolAddress((void**)&qkv, g_qkv);
    cudaGetSymbolAddress((void**)&ao,  g_ao);

    cudaFuncSetAttribute(sgemm_tf32, cudaFuncAttributeMaxDynamicSharedMemorySize,
                         SGEMM_SMEM_BYTES);
    cudaFuncSetAttribute(attn_mma, cudaFuncAttributeMaxDynamicSharedMemorySize,
                         ATTN_SMEM_BYTES);

    // 1) QKV projection
    sgemm_tf32<<<dim3(QKVN / 128, NTOK / 128), 256, SGEMM_SMEM_BYTES>>>(
        X, Wqkv, bqkv, qkv, NTOK, QKVN, DMODEL);
    // 2) Flash attention (tensor cores)
    attn_mma<<<dim3(SEQ / BQ, BATCH * NHEAD), 256, ATTN_SMEM_BYTES>>>(qkv, mask, ao);
    // 3) Output projection
    sgemm_tf32<<<dim3(DMODEL / 128, NTOK / 128), 256, SGEMM_SMEM_BYTES>>>(
        ao, Wproj, bproj, out, NTOK, DMODEL, DMODEL);
}

// round 8
// speedup vs baseline: 3.4120x; 1.1431x over previous
#include <cuda_runtime.h>
#include <math.h>
#include <stdint.h>

// Problem constants
#define BATCH 2
#define SEQ   2048
#define DMODEL 1024
#define NHEAD 16
#define DHEAD 64
#define NTOK  (BATCH*SEQ)          // 4096
#define QKVN  (3*DMODEL)           // 3072

// Scratch (allocation-free rule: __device__ globals)
__device__ float g_qkv[(size_t)NTOK * QKVN];    // [4096][3072] tf32-valued
__device__ float g_ao [(size_t)NTOK * DMODEL];  // [4096][1024] tf32-valued
__device__ float g_xr [(size_t)NTOK * DMODEL];  // rounded X
__device__ float g_wqr[(size_t)QKVN * DMODEL];  // rounded Wqkv
__device__ float g_wpr[(size_t)DMODEL * DMODEL];// rounded Wproj

__device__ __forceinline__ uint32_t f2tf32(float f) {
    uint32_t u;
    asm("cvt.rna.tf32.f32 %0, %1;" : "=r"(u) : "f"(f));
    return u;
}

__device__ __forceinline__ void mma_tf32(float c[4], const uint32_t a[4], const uint32_t b[2]) {
    asm volatile(
        "mma.sync.aligned.m16n8k8.row.col.f32.tf32.tf32.f32 "
        "{%0,%1,%2,%3}, {%4,%5,%6,%7}, {%8,%9}, {%0,%1,%2,%3};"
        : "+f"(c[0]), "+f"(c[1]), "+f"(c[2]), "+f"(c[3])
        : "r"(a[0]), "r"(a[1]), "r"(a[2]), "r"(a[3]), "r"(b[0]), "r"(b[1]));
}

__device__ __forceinline__ void cp_async16(uint32_t smem_addr, const void* gptr) {
    asm volatile("cp.async.ca.shared.global [%0], [%1], 16;\n"
                 :: "r"(smem_addr), "l"(gptr));
}
__device__ __forceinline__ void cp_commit() {
    asm volatile("cp.async.commit_group;\n");
}
__device__ __forceinline__ void cp_wait0() {
    asm volatile("cp.async.wait_group 0;\n");
}

// ---------------------------------------------------------------------------
// Pre-pass: round X, Wqkv, Wproj to tf32-valued fp32 (RNA). One launch.
// ---------------------------------------------------------------------------
#define NX4  (NTOK*DMODEL/4)
#define NWQ4 (QKVN*DMODEL/4)
#define NWP4 (DMODEL*DMODEL/4)

__global__ void prepass_round(const float4* __restrict__ X,
                              const float4* __restrict__ Wq,
                              const float4* __restrict__ Wp,
                              float4* __restrict__ Xr,
                              float4* __restrict__ Wqr,
                              float4* __restrict__ Wpr)
{
    int i = blockIdx.x * blockDim.x + threadIdx.x;
    const float4* src;
    float4* dst;
    if (i < NX4) { src = X + i; dst = Xr + i; }
    else if (i < NX4 + NWQ4) { src = Wq + (i - NX4); dst = Wqr + (i - NX4); }
    else if (i < NX4 + NWQ4 + NWP4) { src = Wp + (i - NX4 - NWQ4); dst = Wpr + (i - NX4 - NWQ4); }
    else return;
    float4 v = *src;
    float4 r;
    r.x = __uint_as_float(f2tf32(v.x));
    r.y = __uint_as_float(f2tf32(v.y));
    r.z = __uint_as_float(f2tf32(v.z));
    r.w = __uint_as_float(f2tf32(v.w));
    *dst = r;
}

// ---------------------------------------------------------------------------
// TF32 GEMM, cp.async double-buffered, ZERO cvt (inputs pre-rounded).
// C[M,N] = A[M,K] @ W[N,K]^T + bias[N].  ROUND_OUT: round C to tf32 values.
// 128x128 tile, BK=32, 256 threads = 8 warps (4x2), warp tile 32x64.
// ---------------------------------------------------------------------------
#define GLD 36
#define SG_STAGE (128*GLD)
#define SGEMM_SMEM_BYTES (4*SG_STAGE*4)

template <bool ROUND_OUT>
__global__ __launch_bounds__(256, 2)
void sgemm_tf32(const float* __restrict__ A, const float* __restrict__ W,
                const float* __restrict__ bias, float* __restrict__ C,
                int M, int N, int K)
{
    extern __shared__ uint32_t sgs[];
    uint32_t* As = sgs;
    uint32_t* Ws = sgs + 2 * SG_STAGE;

    const int tid = threadIdx.x;
    const int l   = tid & 31;
    const int w   = tid >> 5;
    const int wm  = (w & 3) * 32;
    const int wn  = (w >> 2) * 64;
    const int bm  = blockIdx.y * 128;
    const int bn  = blockIdx.x * 128;
    const int g   = l >> 2;
    const int tg  = l & 3;

    const int KT = K >> 5;

    float acc[2][8][4];
    #pragma unroll
    for (int i = 0; i < 2; i++)
        #pragma unroll
        for (int j = 0; j < 8; j++)
            #pragma unroll
            for (int t = 0; t < 4; t++) acc[i][j][t] = 0.f;

    auto issue_stage = [&](int kt, int buf) {
        int k0 = kt << 5;
        #pragma unroll
        for (int it = 0; it < 4; it++) {
            int idx = tid + it * 256;
            int row = idx >> 3;
            int kq  = (idx & 7) << 2;
            uint32_t da = (uint32_t)__cvta_generic_to_shared(
                &As[buf * SG_STAGE + row * GLD + kq]);
            cp_async16(da, &A[(size_t)(bm + row) * K + k0 + kq]);
            uint32_t dw = (uint32_t)__cvta_generic_to_shared(
                &Ws[buf * SG_STAGE + row * GLD + kq]);
            cp_async16(dw, &W[(size_t)(bn + row) * K + k0 + kq]);
        }
        cp_commit();
    };

    issue_stage(0, 0);

    for (int kt = 0; kt < KT; kt++) {
        cp_wait0();
        __syncthreads();
        if (kt + 1 < KT) issue_stage(kt + 1, (kt + 1) & 1);

        const uint32_t* Ab = &As[(kt & 1) * SG_STAGE];
        const uint32_t* Wb = &Ws[(kt & 1) * SG_STAGE];

        #pragma unroll
        for (int ks = 0; ks < 4; ks++) {
            int k8 = ks * 8;
            uint32_t af[2][4];
            #pragma unroll
            for (int mt = 0; mt < 2; mt++) {
                int r0 = wm + mt * 16 + g;
                af[mt][0] = Ab[r0 * GLD + k8 + tg];
                af[mt][1] = Ab[(r0 + 8) * GLD + k8 + tg];
                af[mt][2] = Ab[r0 * GLD + k8 + 4 + tg];
                af[mt][3] = Ab[(r0 + 8) * GLD + k8 + 4 + tg];
            }
            uint32_t bf[8][2];
            #pragma unroll
            for (int nt = 0; nt < 8; nt++) {
                int c0 = wn + nt * 8 + g;
                bf[nt][0] = Wb[c0 * GLD + k8 + tg];
                bf[nt][1] = Wb[c0 * GLD + k8 + 4 + tg];
            }
            #pragma unroll
            for (int mt = 0; mt < 2; mt++)
                #pragma unroll
                for (int nt = 0; nt < 8; nt++)
                    mma_tf32(acc[mt][nt], af[mt], bf[nt]);
        }
        __syncthreads();
    }

    #pragma unroll
    for (int mt = 0; mt < 2; mt++) {
        int row = bm + wm + mt * 16 + g;
        #pragma unroll
        for (int nt = 0; nt < 8; nt++) {
            int col = bn + wn + nt * 8 + tg * 2;
            float b0 = bias[col], b1 = bias[col + 1];
            float v00 = acc[mt][nt][0] + b0, v01 = acc[mt][nt][1] + b1;
            float v10 = acc[mt][nt][2] + b0, v11 = acc[mt][nt][3] + b1;
            if (ROUND_OUT) {
                v00 = __uint_as_float(f2tf32(v00));
                v01 = __uint_as_float(f2tf32(v01));
                v10 = __uint_as_float(f2tf32(v10));
                v11 = __uint_as_float(f2tf32(v11));
            }
            C[(size_t)row * N + col]           = v00;
            C[(size_t)row * N + col + 1]       = v01;
            C[(size_t)(row + 8) * N + col]     = v10;
            C[(size_t)(row + 8) * N + col + 1] = v11;
        }
    }
}

// ---------------------------------------------------------------------------
// Tensor-core flash attention, cp.async double-buffered K/V (raw tf32-valued).
// Block: 256 threads = 8 warps; tile 128 queries x 64 keys; 2 CTAs/SM.
// qkv per token: [H][3*DHEAD]. V fragments read transposed from raw V rows
// (stride 72 -> bank-conflict-free bijection).
// ---------------------------------------------------------------------------
#define BQ 128
#define BK 64
#define APAD 68
#define VPAD 72
#define K_STAGE (64*APAD)
#define V_STAGE (64*VPAD)

// words: Qs/Ps 128*68, Kr 2*64*68, Vr 2*64*72, maskadd 2*64
#define ATTN_SMEM_WORDS (128*APAD + 2*K_STAGE + 2*V_STAGE + 128)
#define ATTN_SMEM_BYTES (ATTN_SMEM_WORDS * 4)

__global__ __launch_bounds__(256, 2)
void attn_mma(const float* __restrict__ qkv,
              const unsigned int* __restrict__ mask,
              float* __restrict__ ao)
{
    extern __shared__ uint32_t smw[];
    uint32_t* Qs = smw;                     // [128][APAD]; becomes Ps
    uint32_t* Kr = smw + 128 * APAD;        // [2][64][APAD] raw K rows
    uint32_t* Vr = Kr + 2 * K_STAGE;        // [2][64][VPAD] raw V rows
    float* maskadd = (float*)(Vr + 2 * V_STAGE); // [2][64]

    const int bh = blockIdx.y;
    const int b  = bh >> 4;
    const int h  = bh & 15;
    const int q0 = blockIdx.x * BQ;
    const int tid = threadIdx.x;
    const int w  = tid >> 5;
    const int l  = tid & 31;
    const int g  = l >> 2;
    const int tg = l & 3;
    const int r0 = w * 16 + g;

    const float scale = 0.03125f;
    const float slope = exp2f(-0.5f * (float)(h + 1));
    const float* base = qkv + (size_t)b * SEQ * QKVN + h * (3 * DHEAD);

    auto issue_kv = [&](int k0, int buf) {
        #pragma unroll
        for (int it = 0; it < 4; it++) {
            int idx = tid + it * 256;       // 1024 chunks per matrix
            int row = idx >> 4;
            int c4  = (idx & 15) << 2;
            const float* kp = &base[(size_t)(k0 + row) * QKVN + DHEAD];
            uint32_t dk = (uint32_t)__cvta_generic_to_shared(
                &Kr[buf * K_STAGE + row * APAD + c4]);
            cp_async16(dk, kp + c4);
            uint32_t dv = (uint32_t)__cvta_generic_to_shared(
                &Vr[buf * V_STAGE + row * VPAD + c4]);
            cp_async16(dv, kp + DHEAD + c4);
        }
        cp_commit();
    };

    // Prologue: prefetch tile 0, mask 0, load Q (scaled; values stay tf32-valued)
    issue_kv(0, 0);
    if (tid < 64)
        maskadd[tid] = mask[b * SEQ + tid] ? 0.f : -3.0e38f;
    #pragma unroll
    for (int it = 0; it < 8; it++) {
        int idx = tid + it * 256;
        int row = idx >> 4;
        int d4  = (idx & 15) << 2;
        float4 v = *(const float4*)&base[(size_t)(q0 + row) * QKVN + d4];
        uint4 u = make_uint4(__float_as_uint(v.x * scale), __float_as_uint(v.y * scale),
                             __float_as_uint(v.z * scale), __float_as_uint(v.w * scale));
        *(uint4*)&Qs[row * APAD + d4] = u;
    }
    __syncthreads();

    uint32_t qa[8][4];
    #pragma unroll
    for (int ks = 0; ks < 8; ks++) {
        int k8 = ks * 8;
        qa[ks][0] = Qs[r0 * APAD + k8 + tg];
        qa[ks][1] = Qs[(r0 + 8) * APAD + k8 + tg];
        qa[ks][2] = Qs[r0 * APAD + k8 + 4 + tg];
        qa[ks][3] = Qs[(r0 + 8) * APAD + k8 + 4 + tg];
    }
    __syncthreads();                        // Qs dead -> Ps
    uint32_t* Ps = Qs;

    float o[8][4];
    #pragma unroll
    for (int nt = 0; nt < 8; nt++)
        #pragma unroll
        for (int c = 0; c < 4; c++) o[nt][c] = 0.f;
    float m0 = -INFINITY, m1 = -INFINITY, l0 = 0.f, l1 = 0.f;

    const int qg0 = q0 + r0;
    const int qg1 = qg0 + 8;
    const int NT = SEQ / BK;

    for (int t = 0; t < NT; t++) {
        const int k0 = t * BK;
        cp_wait0();
        __syncthreads();                    // stage t visible; compute t-1 done
        if (t + 1 < NT) {
            issue_kv(k0 + BK, (t + 1) & 1);
            if (tid < 64)
                maskadd[((t + 1) & 1) * 64 + tid] =
                    mask[b * SEQ + k0 + BK + tid] ? 0.f : -3.0e38f;
        }
        const uint32_t* Kb = &Kr[(t & 1) * K_STAGE];
        const uint32_t* Vb = &Vr[(t & 1) * V_STAGE];
        const float* mb = &maskadd[(t & 1) * 64];

        // --- S = Qs @ K^T (raw fragments) ---
        float s[8][4];
        #pragma unroll
        for (int nt = 0; nt < 8; nt++)
            #pragma unroll
            for (int c = 0; c < 4; c++) s[nt][c] = 0.f;

        #pragma unroll
        for (int ks = 0; ks < 8; ks++) {
            int k8 = ks * 8;
            uint32_t bf[8][2];
            #pragma unroll
            for (int nt = 0; nt < 8; nt++) {
                int c0 = nt * 8 + g;
                bf[nt][0] = Kb[c0 * APAD + k8 + tg];
                bf[nt][1] = Kb[c0 * APAD + k8 + 4 + tg];
            }
            #pragma unroll
            for (int nt = 0; nt < 8; nt++)
                mma_tf32(s[nt], qa[ks], bf[nt]);
        }

        // --- ALiBi + mask, row max ---
        float mx0 = -INFINITY, mx1 = -INFINITY;
        #pragma unroll
        for (int nt = 0; nt < 8; nt++) {
            int lc0 = nt * 8 + 2 * tg;
            int kg0 = k0 + lc0, kg1 = kg0 + 1;
            float ma0 = mb[lc0], ma1 = mb[lc0 + 1];
            s[nt][0] += ma0 - slope * fabsf((float)(qg0 - kg0));
            s[nt][1] += ma1 - slope * fabsf((float)(qg0 - kg1));
            s[nt][2] += ma0 - slope * fabsf((float)(qg1 - kg0));
            s[nt][3] += ma1 - slope * fabsf((float)(qg1 - kg1));
            mx0 = fmaxf(mx0, fmaxf(s[nt][0], s[nt][1]));
            mx1 = fmaxf(mx1, fmaxf(s[nt][2], s[nt][3]));
        }
        mx0 = fmaxf(mx0, __shfl_xor_sync(0xffffffffu, mx0, 1));
        mx0 = fmaxf(mx0, __shfl_xor_sync(0xffffffffu, mx0, 2));
        mx1 = fmaxf(mx1, __shfl_xor_sync(0xffffffffu, mx1, 1));
        mx1 = fmaxf(mx1, __shfl_xor_sync(0xffffffffu, mx1, 2));

        float mn0 = fmaxf(m0, mx0), mn1 = fmaxf(m1, mx1);
        float al0 = __expf(m0 - mn0), al1 = __expf(m1 - mn1);
        m0 = mn0; m1 = mn1;

        // --- exp, row sums, store P (tf32-rounded) ---
        float sum0 = 0.f, sum1 = 0.f;
        #pragma unroll
        for (int nt = 0; nt < 8; nt++) {
            float p00 = __expf(s[nt][0] - mn0);
            float p01 = __expf(s[nt][1] - mn0);
            float p10 = __expf(s[nt][2] - mn1);
            float p11 = __expf(s[nt][3] - mn1);
            sum0 += p00 + p01;
            sum1 += p10 + p11;
            int lc = nt * 8 + 2 * tg;
            *(uint2*)&Ps[r0 * APAD + lc]       = make_uint2(f2tf32(p00), f2tf32(p01));
            *(uint2*)&Ps[(r0 + 8) * APAD + lc] = make_uint2(f2tf32(p10), f2tf32(p11));
        }
        sum0 += __shfl_xor_sync(0xffffffffu, sum0, 1);
        sum0 += __shfl_xor_sync(0xffffffffu, sum0, 2);
        sum1 += __shfl_xor_sync(0xffffffffu, sum1, 1);
        sum1 += __shfl_xor_sync(0xffffffffu, sum1, 2);
        l0 = l0 * al0 + sum0;
        l1 = l1 * al1 + sum1;

        #pragma unroll
        for (int nt = 0; nt < 8; nt++) {
            o[nt][0] *= al0; o[nt][1] *= al0;
            o[nt][2] *= al1; o[nt][3] *= al1;
        }
        __syncwarp();                       // P rows warp-private

        // --- O += P @ V (V fragments transposed from raw rows) ---
        #pragma unroll
        for (int ks = 0; ks < 8; ks++) {
            int k8 = ks * 8;
            uint32_t pa[4];
            pa[0] = Ps[r0 * APAD + k8 + tg];
            pa[1] = Ps[(r0 + 8) * APAD + k8 + tg];
            pa[2] = Ps[r0 * APAD + k8 + 4 + tg];
            pa[3] = Ps[(r0 + 8) * APAD + k8 + 4 + tg];
            uint32_t vf[8][2];
            #pragma unroll
            for (int nt = 0; nt < 8; nt++) {
                int c0 = nt * 8 + g;
                vf[nt][0] = Vb[(k8 + tg) * VPAD + c0];
                vf[nt][1] = Vb[(k8 + 4 + tg) * VPAD + c0];
            }
            #pragma unroll
            for (int nt = 0; nt < 8; nt++)
                mma_tf32(o[nt], pa, vf[nt]);
        }
        // no trailing barrier: buffer t&1 is next written by issue at t+2,
        // which happens after the top-of-loop barrier of iteration t+1.
    }

    // --- Finalize (round ao to tf32 values: it feeds the proj GEMM raw) ---
    float il0 = 1.f / l0, il1 = 1.f / l1;
    #pragma unroll
    for (int nt = 0; nt < 8; nt++) {
        int col = h * DHEAD + nt * 8 + 2 * tg;
        uint2 v0 = make_uint2(f2tf32(o[nt][0] * il0), f2tf32(o[nt][1] * il0));
        uint2 v1 = make_uint2(f2tf32(o[nt][2] * il1), f2tf32(o[nt][3] * il1));
        *(uint2*)&ao[(size_t)(b * SEQ + qg0) * DMODEL + col] = v0;
        *(uint2*)&ao[(size_t)(b * SEQ + qg1) * DMODEL + col] = v1;
    }
}

// ---------------------------------------------------------------------------
extern "C" void kernel_launch(void* const* d_in, const int* in_sizes, int n_in,
                              void* d_out, int out_size)
{
    const float* X     = (const float*)d_in[0];
    const unsigned int* mask = (const unsigned int*)d_in[1];
    const float* Wqkv  = (const float*)d_in[2];
    const float* bqkv  = (const float*)d_in[3];
    const float* Wproj = (const float*)d_in[4];
    const float* bproj = (const float*)d_in[5];
    float* out = (float*)d_out;

    float *qkv, *ao, *xr, *wqr, *wpr;
    cudaGetSymbolAddress((void**)&qkv, g_qkv);
    cudaGetSymbolAddress((void**)&ao,  g_ao);
    cudaGetSymbolAddress((void**)&xr,  g_xr);
    cudaGetSymbolAddress((void**)&wqr, g_wqr);
    cudaGetSymbolAddress((void**)&wpr, g_wpr);

    cudaFuncSetAttribute(sgemm_tf32<true>, cudaFuncAttributeMaxDynamicSharedMemorySize,
                         SGEMM_SMEM_BYTES);
    cudaFuncSetAttribute(sgemm_tf32<false>, cudaFuncAttributeMaxDynamicSharedMemorySize,
                         SGEMM_SMEM_BYTES);
    cudaFuncSetAttribute(attn_mma, cudaFuncAttributeMaxDynamicSharedMemorySize,
                         ATTN_SMEM_BYTES);

    // 0) Round all GEMM inputs to tf32 values (RNA)
    int tot4 = NX4 + NWQ4 + NWP4;
    prepass_round<<<(tot4 + 255) / 256, 256>>>(
        (const float4*)X, (const float4*)Wqkv, (const float4*)Wproj,
        (float4*)xr, (float4*)wqr, (float4*)wpr);

    // 1) QKV projection (output rounded: feeds attention MMAs raw)
    sgemm_tf32<true><<<dim3(QKVN / 128, NTOK / 128), 256, SGEMM_SMEM_BYTES>>>(
        xr, wqr, bqkv, qkv, NTOK, QKVN, DMODEL);
    // 2) Flash attention (tensor cores, cp.async K/V pipeline)
    attn_mma<<<dim3(SEQ / BQ, BATCH * NHEAD), 256, ATTN_SMEM_BYTES>>>(qkv, mask, ao);
    // 3) Output projection (full fp32 output)
    sgemm_tf32<false><<<dim3(DMODEL / 128, NTOK / 128), 256, SGEMM_SMEM_BYTES>>>(
        ao, wpr, bproj, out, NTOK, DMODEL, DMODEL);
}